// round 1
// baseline (speedup 1.0000x reference)
#include <cuda_runtime.h>
#include <cuda_bf16.h>

// db4-style lowpass coefficients (DEC_LO)
#define D0 (-0.010597401784997278f)
#define D1 ( 0.032883011666982945f)
#define D2 ( 0.030841381835986965f)
#define D3 (-0.18703481171888114f)
#define D4 (-0.02798376941698385f)
#define D5 ( 0.6308807679295904f)
#define D6 ( 0.7148465705525415f)
#define D7 ( 0.23037781330885523f)

// Analysis filter h[t] = DEC_LO[7-t]
#define H0 D7
#define H1 D6
#define H2 D5
#define H3 D4
#define H4 D3
#define H5 D2
#define H6 D1
#define H7 D0

// Level lengths
constexpr int N0 = 32768;
constexpr int N1 = 16387;
constexpr int N2 = 8197;
constexpr int N3 = 4102;
constexpr int N4 = 2054;

// Shared buffer sizes (with slack for synthesis outputs 16388 / 8198)
constexpr int SZ1 = 16392;
constexpr int SZ2 = 8200;
constexpr int SZ3 = 4104;
constexpr int SZ4 = 2056;
constexpr int SMEM_FLOATS = SZ1 + SZ2 + SZ3 + SZ4;  // 30752 -> 123008 B

constexpr int ROWS = 512;        // 32 * 16
constexpr int NTHREADS = 512;

// Analysis step: out[o] = sum_t h[t] * in[2o + t - 6], zero-extended input.
__device__ __forceinline__ void afb_smem(const float* __restrict__ in, int Nin,
                                         float* __restrict__ out, int Nout,
                                         int tid, int nt) {
    for (int o = tid; o < Nout; o += nt) {
        int base = 2 * o - 6;
        float acc = 0.f;
        // guarded (predicated) loads; only edges actually predicate off
        #pragma unroll
        for (int t = 0; t < 8; ++t) {
            int i = base + t;
            float v = ((unsigned)i < (unsigned)Nin) ? in[i] : 0.f;
            const float h[8] = {H0, H1, H2, H3, H4, H5, H6, H7};
            acc = fmaf(h[t], v, acc);
        }
        out[o] = acc;
    }
}

// Synthesis step (upsample-by-2, pad(1,1), 8-tap): out[o] uses in[b..b+3], b = o>>1.
// even o: taps d1,d3,d5,d7 ; odd o: taps d0,d2,d4,d6.  Always in-bounds by construction.
__device__ __forceinline__ void sfb_smem(const float* __restrict__ in,
                                         float* __restrict__ out, int Nout,
                                         int tid, int nt) {
    for (int o = tid; o < Nout; o += nt) {
        int b = o >> 1;
        float v0 = in[b], v1 = in[b + 1], v2 = in[b + 2], v3 = in[b + 3];
        float acc;
        if (o & 1)
            acc = fmaf(D0, v0, fmaf(D2, v1, fmaf(D4, v2, D6 * v3)));
        else
            acc = fmaf(D1, v0, fmaf(D3, v1, fmaf(D5, v2, D7 * v3)));
        out[o] = acc;
    }
}

__global__ __launch_bounds__(NTHREADS, 1)
void WT_series_decomp_kernel(const float* __restrict__ x,
                             float* __restrict__ season,
                             float* __restrict__ trend) {
    extern __shared__ float sm[];
    float* B1 = sm;              // lo1, then t1 (16388)
    float* B2 = B1 + SZ1;        // lo2, then t2 (8198)
    float* B3 = B2 + SZ2;        // lo3, then t3 (4102)
    float* B4 = B3 + SZ3;        // lo4 (2054)

    const int row = blockIdx.x;
    const float* __restrict__ xr = x + (size_t)row * N0;
    float* __restrict__ sr = season + (size_t)row * N0;
    float* __restrict__ tr = trend  + (size_t)row * N0;
    const int tid = threadIdx.x;
    const int nt  = blockDim.x;

    // ---- Analysis: level 1 from global ----
    for (int o = tid; o < N1; o += nt) {
        int base = 2 * o - 6;
        float acc = 0.f;
        const float h[8] = {H0, H1, H2, H3, H4, H5, H6, H7};
        #pragma unroll
        for (int t = 0; t < 8; ++t) {
            int i = base + t;
            float v = ((unsigned)i < (unsigned)N0) ? __ldg(xr + i) : 0.f;
            acc = fmaf(h[t], v, acc);
        }
        B1[o] = acc;
    }
    __syncthreads();

    // ---- Analysis: levels 2..4 in shared ----
    afb_smem(B1, N1, B2, N2, tid, nt);
    __syncthreads();
    afb_smem(B2, N2, B3, N3, tid, nt);
    __syncthreads();
    afb_smem(B3, N3, B4, N4, tid, nt);
    __syncthreads();

    // ---- Synthesis: lo4(2054) -> t3(4102) into B3 (lo3 dead) ----
    sfb_smem(B4, B3, N3 /*4102*/, tid, nt);
    __syncthreads();
    // t3(4102) -> t2(8198) into B2 (lo2 dead)
    sfb_smem(B3, B2, 8198, tid, nt);
    __syncthreads();
    // t2 trimmed to 8197 -> t1(16388) into B1 (lo1 dead). Trim is implicit:
    // max index read = (16387>>1)+3 = 8196 < 8197.
    sfb_smem(B2, B1, 16388, tid, nt);
    __syncthreads();

    // ---- Final: t1 trimmed to 16387 -> trend(32768); season = x - trend ----
    for (int o = tid; o < N0; o += nt) {
        int b = o >> 1;                     // max 16383, reads up to 16386 < 16387
        float v0 = B1[b], v1 = B1[b + 1], v2 = B1[b + 2], v3 = B1[b + 3];
        float t;
        if (o & 1)
            t = fmaf(D0, v0, fmaf(D2, v1, fmaf(D4, v2, D6 * v3)));
        else
            t = fmaf(D1, v0, fmaf(D3, v1, fmaf(D5, v2, D7 * v3)));
        tr[o] = t;
        sr[o] = __ldg(xr + o) - t;
    }
}

extern "C" void kernel_launch(void* const* d_in, const int* in_sizes, int n_in,
                              void* d_out, int out_size) {
    const float* x = (const float*)d_in[0];
    float* out = (float*)d_out;
    float* season = out;                                   // tuple element 0
    float* trend  = out + (size_t)ROWS * N0;               // tuple element 1

    const size_t smem = (size_t)SMEM_FLOATS * sizeof(float);
    cudaFuncSetAttribute(WT_series_decomp_kernel,
                         cudaFuncAttributeMaxDynamicSharedMemorySize, (int)smem);
    WT_series_decomp_kernel<<<ROWS, NTHREADS, smem>>>(x, season, trend);
}

// round 2
// speedup vs baseline: 1.7423x; 1.7423x over previous
#include <cuda_runtime.h>
#include <cuda_bf16.h>

// db4-style lowpass coefficients (DEC_LO)
#define D0 (-0.010597401784997278f)
#define D1 ( 0.032883011666982945f)
#define D2 ( 0.030841381835986965f)
#define D3 (-0.18703481171888114f)
#define D4 (-0.02798376941698385f)
#define D5 ( 0.6308807679295904f)
#define D6 ( 0.7148465705525415f)
#define D7 ( 0.23037781330885523f)

// Analysis filter h[t] = DEC_LO[7-t]
#define H0 D7
#define H1 D6
#define H2 D5
#define H3 D4
#define H4 D3
#define H5 D2
#define H6 D1
#define H7 D0

// Level lengths (global)
constexpr int N0 = 32768;
constexpr int N1 = 16387;
constexpr int N2 = 8197;
constexpr int N3 = 4102;
constexpr int N4 = 2054;

constexpr int ROWS = 512;      // 32 * 16
constexpr int T    = 4096;     // output tile per CTA
constexpr int TILES = N0 / T;  // 8
constexpr int NTHREADS = 256;

// Shared regions (floats), each with an 8-float front apron inside the region.
// Core capacities (worst-case counts + 8 tail-zero slack):
//   x:   4282 + 8 -> 4312 region (8 apron + 4304)
//   lo1: 2138 / t1: 2051 -> 2176
//   lo2: 1066 / t2: 1029 -> 1104
//   lo3:  530 / t3:  518 -> 560
//   lo4:  262            -> 288
constexpr int RX  = 4320;
constexpr int R1  = 2176;
constexpr int R2  = 1104;
constexpr int R3  = 560;
constexpr int R4  = 288;
constexpr int SMEM_FLOATS = RX + R1 + R2 + R3 + R4;   // 8448 floats = 33792 B

// Analysis stage from smem: out[idx] = lo[os+idx], reading Pin at global base gs.
// Loop bound ocnt+8 writes 8 trailing zeros (tail apron for the next stage).
__device__ __forceinline__ void afb_stage(const float* __restrict__ Pin, int gs,
                                          float* __restrict__ Pout, int os, int ocnt,
                                          int tid, int nt, bool tail_zeros) {
    int total = ocnt + (tail_zeros ? 8 : 0);
    for (int idx = tid; idx < total; idx += nt) {
        float acc = 0.f;
        if (idx < ocnt) {
            int r = 2 * (os + idx) - 6 - gs;       // even offset, aligned float2
            float2 a = *(const float2*)(Pin + r);
            float2 b = *(const float2*)(Pin + r + 2);
            float2 c = *(const float2*)(Pin + r + 4);
            float2 d = *(const float2*)(Pin + r + 6);
            acc = fmaf(H0, a.x, fmaf(H1, a.y,
                  fmaf(H2, b.x, fmaf(H3, b.y,
                  fmaf(H4, c.x, fmaf(H5, c.y,
                  fmaf(H6, d.x,      H7 * d.y)))))));
        }
        Pout[idx] = acc;
    }
}

// Synthesis stage: out global [os, os+ocnt), input stored at global base gs.
__device__ __forceinline__ void sfb_stage(const float* __restrict__ Pin, int gs,
                                          float* __restrict__ Pout, int os, int ocnt,
                                          int tid, int nt) {
    for (int idx = tid; idx < ocnt; idx += nt) {
        int o = os + idx;
        int r = (o >> 1) - gs;
        float v0 = Pin[r], v1 = Pin[r + 1], v2 = Pin[r + 2], v3 = Pin[r + 3];
        float acc;
        if (o & 1)
            acc = fmaf(D0, v0, fmaf(D2, v1, fmaf(D4, v2, D6 * v3)));
        else
            acc = fmaf(D1, v0, fmaf(D3, v1, fmaf(D5, v2, D7 * v3)));
        Pout[idx] = acc;
    }
}

__global__ __launch_bounds__(NTHREADS, 6)
void WT_series_decomp_kernel(const float* __restrict__ x,
                             float* __restrict__ season,
                             float* __restrict__ trend) {
    __shared__ float SM[SMEM_FLOATS];
    float* BX = SM + 8;
    float* B1 = SM + RX + 8;
    float* B2 = SM + RX + R1 + 8;
    float* B3 = SM + RX + R1 + R2 + 8;
    float* B4 = SM + RX + R1 + R2 + R3 + 8;

    const int row  = blockIdx.x >> 3;      // TILES == 8
    const int tile = blockIdx.x & 7;
    const int A = tile * T;
    const int B = A + T;

    const float* __restrict__ xr = x + (size_t)row * N0;
    float* __restrict__ sr = season + (size_t)row * N0;
    float* __restrict__ tr = trend  + (size_t)row * N0;
    const int tid = threadIdx.x;
    const int nt  = NTHREADS;

    // ---- Needed global ranges (inclusive) ----
    const int s1 = A >> 1,  e1 = ((B - 1) >> 1) + 3;      // t1
    const int s2 = s1 >> 1, e2 = (e1 >> 1) + 3;           // t2
    const int s3 = s2 >> 1, e3 = (e2 >> 1) + 3;           // t3
    const int s4 = s3 >> 1, e4 = (e3 >> 1) + 3;           // lo4 (<= N4-1 by construction)

    // Analysis stored ranges (starts are even)
    const int ls3 = max(0, 2 * s4 - 6),  le3 = min(N3 - 1, 2 * e4 + 1);
    const int ls2 = max(0, 2 * ls3 - 6), le2 = min(N2 - 1, 2 * le3 + 1);
    const int ls1 = max(0, 2 * ls2 - 6), le1 = min(N1 - 1, 2 * le2 + 1);
    const int xs  = max(0, 2 * ls1 - 6), xe  = min(N0 - 1, 2 * le1 + 1);

    const int xcnt  = xe - xs + 1;
    const int c1    = le1 - ls1 + 1;
    const int c2    = le2 - ls2 + 1;
    const int c3    = le3 - ls3 + 1;
    const int c4    = e4 - s4 + 1;

    // ---- Front aprons (zeros) for analysis-input buffers ----
    if (tid < 8) {
        BX[tid - 8] = 0.f; B1[tid - 8] = 0.f; B2[tid - 8] = 0.f; B3[tid - 8] = 0.f;
    }

    // ---- Load x tile into smem (+8 tail zeros) ----
    for (int idx = tid; idx < xcnt + 8; idx += nt)
        BX[idx] = (idx < xcnt) ? __ldg(xr + xs + idx) : 0.f;
    __syncthreads();

    // ---- Analysis ----
    afb_stage(BX, xs,  B1, ls1, c1, tid, nt, true);
    __syncthreads();
    afb_stage(B1, ls1, B2, ls2, c2, tid, nt, true);
    __syncthreads();
    afb_stage(B2, ls2, B3, ls3, c3, tid, nt, true);
    __syncthreads();
    afb_stage(B3, ls3, B4, s4,  c4, tid, nt, false);
    __syncthreads();

    // ---- Synthesis (overwrite dead analysis buffers) ----
    sfb_stage(B4, s4, B3, s3, e3 - s3 + 1, tid, nt);   // t3 over lo3
    __syncthreads();
    sfb_stage(B3, s3, B2, s2, e2 - s2 + 1, tid, nt);   // t2 over lo2
    __syncthreads();
    sfb_stage(B2, s2, B1, s1, e1 - s1 + 1, tid, nt);   // t1 over lo1
    __syncthreads();

    // ---- Final: trend + season, even/odd pairs, float2 global stores ----
    for (int idx = tid; idx < (T >> 1); idx += nt) {
        int o = A + 2 * idx;                  // even
        int r = (o >> 1) - s1;
        float v0 = B1[r], v1 = B1[r + 1], v2 = B1[r + 2], v3 = B1[r + 3];
        float te = fmaf(D1, v0, fmaf(D3, v1, fmaf(D5, v2, D7 * v3)));
        float to = fmaf(D0, v0, fmaf(D2, v1, fmaf(D4, v2, D6 * v3)));
        float2 xv = *(const float2*)(BX + (o - xs));   // o-xs even -> aligned
        *(float2*)(tr + o) = make_float2(te, to);
        *(float2*)(sr + o) = make_float2(xv.x - te, xv.y - to);
    }
}

extern "C" void kernel_launch(void* const* d_in, const int* in_sizes, int n_in,
                              void* d_out, int out_size) {
    const float* x = (const float*)d_in[0];
    float* out = (float*)d_out;
    float* season = out;                       // tuple element 0
    float* trend  = out + (size_t)ROWS * N0;   // tuple element 1

    WT_series_decomp_kernel<<<ROWS * TILES, NTHREADS>>>(x, season, trend);
}